// round 1
// baseline (speedup 1.0000x reference)
#include <cuda_runtime.h>

#define HN_B      2
#define HN_H      480
#define HN_W      640
#define HN_C      22
#define HN_HW     (HN_H * HN_W)          // 307200
#define HN_SKIP   20
#define HN_P      (HN_HW / HN_SKIP)      // 15360
#define HN_NSTEPS 200
#define HN_STEP   4.0f
#define HN_BC     (HN_B * HN_C)          // 44
#define HN_HOUGH_N ((size_t)HN_B * HN_C * HN_HW)   // 13,516,800

// Scratch (device globals; no allocation allowed in kernel_launch)
__device__ unsigned int g_hough[HN_B * HN_C * HN_HW];
__device__ float4       g_pts[HN_B * HN_P];   // dnx, dny, z, label(bits)
__device__ int          g_pk[HN_BC];
__device__ unsigned int g_vmax[HN_BC];
__device__ float        g_zsum[HN_BC];
__device__ float        g_ninl[HN_BC];
__device__ unsigned int g_counts[HN_BC];

// ---------------------------------------------------------------------------
// K0: zero the hough accumulator (vectorized) + small accumulators
// ---------------------------------------------------------------------------
__global__ void hn_zero_kernel() {
    size_t n4 = HN_HOUGH_N / 4;
    uint4* h4 = reinterpret_cast<uint4*>(g_hough);
    size_t stride = (size_t)gridDim.x * blockDim.x;
    uint4 z4 = make_uint4(0u, 0u, 0u, 0u);
    for (size_t i = (size_t)blockIdx.x * blockDim.x + threadIdx.x; i < n4; i += stride)
        h4[i] = z4;
    int tid = blockIdx.x * blockDim.x + threadIdx.x;
    if (tid < HN_BC) {
        g_zsum[tid]   = 0.0f;
        g_ninl[tid]   = 0.0f;
        g_counts[tid] = 0u;
    }
}

// ---------------------------------------------------------------------------
// K1: per-point setup + hough voting. One warp per sampled point;
//     lanes split the 200 ray steps.
// ---------------------------------------------------------------------------
__global__ void hn_vote_kernel(const int* __restrict__ label_2d,
                               const float* __restrict__ vertex_pred) {
    int gwarp = (blockIdx.x * blockDim.x + threadIdx.x) >> 5;
    int lane  = threadIdx.x & 31;
    if (gwarp >= HN_B * HN_P) return;

    int b = gwarp / HN_P;
    int p = gwarp % HN_P;
    int idx = p * HN_SKIP;
    float xs = (float)(idx % HN_W);
    float ys = (float)(idx / HN_W);

    int label = label_2d[b * HN_HW + idx];
    const float* vp = vertex_pred + ((size_t)(b * HN_HW + idx)) * (3 * HN_C) + label * 3;
    float dx = vp[0], dy = vp[1], z = vp[2];

    // dn = d / (||d|| + 1e-9), strict per-op rounding (no FMA contraction)
    float nrm = __fadd_rn(__fsqrt_rn(__fadd_rn(__fmul_rn(dx, dx), __fmul_rn(dy, dy))), 1e-9f);
    float dnx = __fdiv_rn(dx, nrm);
    float dny = __fdiv_rn(dy, nrm);

    if (lane == 0) {
        float4 pt;
        pt.x = dnx; pt.y = dny; pt.z = z; pt.w = __int_as_float(label);
        g_pts[gwarp] = pt;
    }

    if (label <= 0) return;

    unsigned int* hbase = g_hough + (size_t)(b * HN_C + label) * HN_HW;
    #pragma unroll
    for (int i = lane; i < HN_NSTEPS; i += 32) {
        float t  = (float)(i + 1) * HN_STEP;               // exact small ints
        float cx = __fadd_rn(xs, __fmul_rn(dnx, t));
        float cy = __fadd_rn(ys, __fmul_rn(dny, t));
        int cxi = (int)rintf(cx);                          // round-half-even == jnp.round
        int cyi = (int)rintf(cy);
        if (cxi >= 0 && cxi < HN_W && cyi >= 0 && cyi < HN_H)
            atomicAdd(&hbase[cyi * HN_W + cxi], 1u);
    }
}

// ---------------------------------------------------------------------------
// K2: full-image label histogram (counts per (b, c))
// ---------------------------------------------------------------------------
__global__ void hn_counts_kernel(const int* __restrict__ label_2d) {
    __shared__ unsigned int s[HN_BC];
    for (int i = threadIdx.x; i < HN_BC; i += blockDim.x) s[i] = 0u;
    __syncthreads();
    int stride = gridDim.x * blockDim.x;
    for (int i = blockIdx.x * blockDim.x + threadIdx.x; i < HN_B * HN_HW; i += stride) {
        int b = i / HN_HW;
        atomicAdd(&s[b * HN_C + label_2d[i]], 1u);
    }
    __syncthreads();
    for (int i = threadIdx.x; i < HN_BC; i += blockDim.x)
        if (s[i]) atomicAdd(&g_counts[i], s[i]);
}

// ---------------------------------------------------------------------------
// K3: argmax over HW per (b,c), first-index tie-break (matches jnp.argmax)
// ---------------------------------------------------------------------------
__global__ void hn_argmax_kernel() {
    int bc = blockIdx.x;
    const unsigned int* h = g_hough + (size_t)bc * HN_HW;

    unsigned int bv = 0u;
    int bi = -1;
    for (int i = threadIdx.x; i < HN_HW; i += blockDim.x) {
        unsigned int v = h[i];
        if (bi < 0 || v > bv) { bv = v; bi = i; }   // ascending scan keeps earliest max
    }

    __shared__ unsigned int sv[512];
    __shared__ int          si[512];
    sv[threadIdx.x] = bv;
    si[threadIdx.x] = bi;
    __syncthreads();
    for (int s = 256; s > 0; s >>= 1) {
        if (threadIdx.x < s) {
            unsigned int v2 = sv[threadIdx.x + s];
            int          i2 = si[threadIdx.x + s];
            if (v2 > sv[threadIdx.x] ||
                (v2 == sv[threadIdx.x] && i2 < si[threadIdx.x])) {
                sv[threadIdx.x] = v2;
                si[threadIdx.x] = i2;
            }
        }
        __syncthreads();
    }
    if (threadIdx.x == 0) {
        g_pk[bc]   = si[0];
        g_vmax[bc] = sv[0];
    }
}

// ---------------------------------------------------------------------------
// K4: inlier test per point, accumulate z_sum / n_inl per (b, c)
// ---------------------------------------------------------------------------
__global__ void hn_inlier_kernel() {
    __shared__ float s_z[HN_BC];
    __shared__ float s_n[HN_BC];
    for (int i = threadIdx.x; i < HN_BC; i += blockDim.x) { s_z[i] = 0.0f; s_n[i] = 0.0f; }
    __syncthreads();

    int g = blockIdx.x * blockDim.x + threadIdx.x;
    if (g < HN_B * HN_P) {
        int b = g / HN_P;
        int p = g % HN_P;
        int idx = p * HN_SKIP;
        float xs = (float)(idx % HN_W);
        float ys = (float)(idx / HN_W);

        float4 pt = g_pts[g];
        int label = __float_as_int(pt.w);
        if (label > 0) {
            int pk = g_pk[b * HN_C + label];
            float pkx = (float)(pk % HN_W);
            float pky = (float)(pk / HN_W);
            float ddx = __fsub_rn(pkx, xs);
            float ddy = __fsub_rn(pky, ys);
            float nrm = __fadd_rn(__fsqrt_rn(__fadd_rn(__fmul_rn(ddx, ddx),
                                                       __fmul_rn(ddy, ddy))), 1e-9f);
            float dvx = __fdiv_rn(ddx, nrm);
            float dvy = __fdiv_rn(ddy, nrm);
            float dot = __fadd_rn(__fmul_rn(pt.x, dvx), __fmul_rn(pt.y, dvy));
            if (dot > 0.9f) {
                atomicAdd(&s_z[b * HN_C + label], pt.z);
                atomicAdd(&s_n[b * HN_C + label], 1.0f);
            }
        }
    }
    __syncthreads();
    for (int i = threadIdx.x; i < HN_BC; i += blockDim.x) {
        if (s_n[i] != 0.0f) {
            atomicAdd(&g_zsum[i], s_z[i]);
            atomicAdd(&g_ninl[i], s_n[i]);
        }
    }
}

// ---------------------------------------------------------------------------
// K5: finalize — rois + pose per (b, c)
// ---------------------------------------------------------------------------
__global__ void hn_finalize_kernel(const float* __restrict__ extents,
                                   const float* __restrict__ meta,
                                   float* __restrict__ out) {
    int i = threadIdx.x;
    if (i >= HN_BC) return;
    int b = i / HN_C;
    int c = i % HN_C;

    float cnt   = (float)g_counts[i];
    float vmask = (cnt >= 500.0f && c > 0) ? 1.0f : 0.0f;

    int pk = g_pk[i];
    float pkx  = (float)(pk % HN_W);
    float pky  = (float)(pk / HN_W);
    float vmax = (float)g_vmax[i];

    float zs = g_zsum[i];
    float ni = g_ninl[i];
    float depth  = zs / fmaxf(ni, 1.0f);
    float z_safe = (fabsf(depth) > 0.001f) ? depth : 1.0f;

    float fx = meta[b * 48 + 0];
    float fy = meta[b * 48 + 4];
    float e0 = extents[c * 3 + 0], e1 = extents[c * 3 + 1], e2 = extents[c * 3 + 2];
    float diam = sqrtf(e0 * e0 + e1 * e1 + e2 * e2);
    float half_w = 0.5f * diam * fx / z_safe;
    float half_h = 0.5f * diam * fy / z_safe;

    float* o = out + (size_t)i * 14;
    o[0] = (float)b * vmask;
    o[1] = (float)c * vmask;
    o[2] = (pkx - half_w) * vmask;
    o[3] = (pky - half_h) * vmask;
    o[4] = (pkx + half_w) * vmask;
    o[5] = (pky + half_h) * vmask;
    o[6] = vmax * vmask;
    o[7] = vmask;          // quat = (1,0,0,0) * vmask
    o[8] = 0.0f;
    o[9] = 0.0f;
    o[10] = 0.0f;
    const float* K = meta + b * 48 + 9;   // Kinv row-major 3x3
    #pragma unroll
    for (int j = 0; j < 3; j++) {
        float ray = K[j * 3 + 0] * pkx + K[j * 3 + 1] * pky + K[j * 3 + 2];
        o[11 + j] = depth * ray * vmask;
    }
}

// ---------------------------------------------------------------------------
extern "C" void kernel_launch(void* const* d_in, const int* in_sizes, int n_in,
                              void* d_out, int out_size) {
    const int*   label   = (const int*)d_in[0];
    const float* vp      = (const float*)d_in[1];
    const float* extents = (const float*)d_in[2];
    // d_in[3] = poses (unused by reference)
    const float* meta    = (const float*)d_in[4];
    float* out = (float*)d_out;

    // K0: zero accumulators
    {
        int n4 = (int)(HN_HOUGH_N / 4);
        int blocks = (n4 + 255) / 256;
        hn_zero_kernel<<<blocks, 256>>>();
    }
    // K1: vote (one warp per point)
    {
        int warps = HN_B * HN_P;
        int blocks = (warps * 32 + 255) / 256;
        hn_vote_kernel<<<blocks, 256>>>(label, vp);
    }
    // K2: label histogram
    hn_counts_kernel<<<240, 256>>>(label);
    // K3: argmax per (b,c)
    hn_argmax_kernel<<<HN_BC, 512>>>();
    // K4: inlier accumulation
    {
        int blocks = (HN_B * HN_P + 255) / 256;
        hn_inlier_kernel<<<blocks, 256>>>();
    }
    // K5: finalize
    hn_finalize_kernel<<<1, 64>>>(extents, meta, out);
}

// round 2
// speedup vs baseline: 1.4020x; 1.4020x over previous
#include <cuda_runtime.h>

#define HN_B      2
#define HN_H      480
#define HN_W      640
#define HN_C      22
#define HN_HW     (HN_H * HN_W)          // 307200
#define HN_SKIP   20
#define HN_P      (HN_HW / HN_SKIP)      // 15360
#define HN_NSTEPS 200
#define HN_STEP   4.0f
#define HN_BC     (HN_B * HN_C)          // 44
#define HN_HOUGH_N ((size_t)HN_B * HN_C * HN_HW)   // 13,516,800

#define HN_SPLIT  32                     // chunks per plane for argmax pass 1
#define HN_CHUNK4 (HN_HW / 4 / HN_SPLIT) // 2400 uint4 per chunk

// Scratch (device globals; no allocation allowed in kernel_launch)
__device__ unsigned int g_hough[HN_B * HN_C * HN_HW];
__device__ float4       g_pts[HN_B * HN_P];   // dnx, dny, z, label(bits)
__device__ int          g_pk[HN_BC];
__device__ unsigned int g_vmax[HN_BC];
__device__ float        g_zsum[HN_BC];
__device__ float        g_ninl[HN_BC];
__device__ unsigned int g_counts[HN_BC];
__device__ int          g_pval[HN_BC * HN_SPLIT];
__device__ int          g_pidx[HN_BC * HN_SPLIT];

// ---------------------------------------------------------------------------
// K0: zero the hough accumulator (vectorized) + small accumulators
// ---------------------------------------------------------------------------
__global__ void hn_zero_kernel() {
    size_t n4 = HN_HOUGH_N / 4;
    uint4* h4 = reinterpret_cast<uint4*>(g_hough);
    size_t stride = (size_t)gridDim.x * blockDim.x;
    uint4 z4 = make_uint4(0u, 0u, 0u, 0u);
    for (size_t i = (size_t)blockIdx.x * blockDim.x + threadIdx.x; i < n4; i += stride)
        h4[i] = z4;
    int tid = blockIdx.x * blockDim.x + threadIdx.x;
    if (tid < HN_BC) {
        g_zsum[tid]   = 0.0f;
        g_ninl[tid]   = 0.0f;
        g_counts[tid] = 0u;
    }
}

// ---------------------------------------------------------------------------
// K1: per-point setup + hough voting. One warp per sampled point;
//     lanes split the 200 ray steps.
// ---------------------------------------------------------------------------
__global__ void hn_vote_kernel(const int* __restrict__ label_2d,
                               const float* __restrict__ vertex_pred) {
    int gwarp = (blockIdx.x * blockDim.x + threadIdx.x) >> 5;
    int lane  = threadIdx.x & 31;
    if (gwarp >= HN_B * HN_P) return;

    int b = gwarp / HN_P;
    int p = gwarp % HN_P;
    int idx = p * HN_SKIP;
    float xs = (float)(idx % HN_W);
    float ys = (float)(idx / HN_W);

    int label = label_2d[b * HN_HW + idx];
    const float* vp = vertex_pred + ((size_t)(b * HN_HW + idx)) * (3 * HN_C) + label * 3;
    float dx = vp[0], dy = vp[1], z = vp[2];

    // dn = d / (||d|| + 1e-9), strict per-op rounding (no FMA contraction)
    float nrm = __fadd_rn(__fsqrt_rn(__fadd_rn(__fmul_rn(dx, dx), __fmul_rn(dy, dy))), 1e-9f);
    float dnx = __fdiv_rn(dx, nrm);
    float dny = __fdiv_rn(dy, nrm);

    if (lane == 0) {
        float4 pt;
        pt.x = dnx; pt.y = dny; pt.z = z; pt.w = __int_as_float(label);
        g_pts[gwarp] = pt;
    }

    if (label <= 0) return;

    unsigned int* hbase = g_hough + (size_t)(b * HN_C + label) * HN_HW;
    #pragma unroll
    for (int i = lane; i < HN_NSTEPS; i += 32) {
        float t  = (float)(i + 1) * HN_STEP;               // exact small ints
        float cx = __fadd_rn(xs, __fmul_rn(dnx, t));
        float cy = __fadd_rn(ys, __fmul_rn(dny, t));
        int cxi = (int)rintf(cx);                          // round-half-even == jnp.round
        int cyi = (int)rintf(cy);
        if (cxi >= 0 && cxi < HN_W && cyi >= 0 && cyi < HN_H)
            atomicAdd(&hbase[cyi * HN_W + cxi], 1u);
    }
}

// ---------------------------------------------------------------------------
// K2: full-image label histogram (counts per (b, c))
// ---------------------------------------------------------------------------
__global__ void hn_counts_kernel(const int* __restrict__ label_2d) {
    __shared__ unsigned int s[HN_BC];
    for (int i = threadIdx.x; i < HN_BC; i += blockDim.x) s[i] = 0u;
    __syncthreads();
    int stride = gridDim.x * blockDim.x;
    for (int i = blockIdx.x * blockDim.x + threadIdx.x; i < HN_B * HN_HW; i += stride) {
        int b = i / HN_HW;
        atomicAdd(&s[b * HN_C + label_2d[i]], 1u);
    }
    __syncthreads();
    for (int i = threadIdx.x; i < HN_BC; i += blockDim.x)
        if (s[i]) atomicAdd(&g_counts[i], s[i]);
}

// ---------------------------------------------------------------------------
// K3a: argmax pass 1 — 44 planes x 32 chunks, uint4 loads, block reduce.
//      First-index tie-break: ascending scan + strict '>' keeps earliest;
//      cross-thread reduce prefers smaller index on equal value.
// ---------------------------------------------------------------------------
__global__ void hn_argmax1_kernel() {
    int part  = blockIdx.x;              // 0 .. 44*32-1
    int bc    = part / HN_SPLIT;
    int chunk = part % HN_SPLIT;

    const uint4* h4 = reinterpret_cast<const uint4*>(g_hough)
                    + (size_t)bc * (HN_HW / 4) + (size_t)chunk * HN_CHUNK4;
    int base = chunk * HN_CHUNK4 * 4;    // element index within plane

    int bv = -1;
    int bi = 0;
    for (int i = threadIdx.x; i < HN_CHUNK4; i += blockDim.x) {
        uint4 v = h4[i];
        int e = base + i * 4;
        if ((int)v.x > bv) { bv = (int)v.x; bi = e; }
        if ((int)v.y > bv) { bv = (int)v.y; bi = e + 1; }
        if ((int)v.z > bv) { bv = (int)v.z; bi = e + 2; }
        if ((int)v.w > bv) { bv = (int)v.w; bi = e + 3; }
    }

    __shared__ int sv[256];
    __shared__ int si[256];
    sv[threadIdx.x] = bv;
    si[threadIdx.x] = bi;
    __syncthreads();
    for (int s = 128; s > 0; s >>= 1) {
        if (threadIdx.x < s) {
            int v2 = sv[threadIdx.x + s];
            int i2 = si[threadIdx.x + s];
            if (v2 > sv[threadIdx.x] ||
                (v2 == sv[threadIdx.x] && i2 < si[threadIdx.x])) {
                sv[threadIdx.x] = v2;
                si[threadIdx.x] = i2;
            }
        }
        __syncthreads();
    }
    if (threadIdx.x == 0) {
        g_pval[part] = sv[0];
        g_pidx[part] = si[0];
    }
}

// ---------------------------------------------------------------------------
// K3b: argmax pass 2 — one warp per plane, shuffle reduce of 32 partials.
// ---------------------------------------------------------------------------
__global__ void hn_argmax2_kernel() {
    int bc   = blockIdx.x;
    int lane = threadIdx.x;              // 0..31 == HN_SPLIT
    int v = g_pval[bc * HN_SPLIT + lane];
    int i = g_pidx[bc * HN_SPLIT + lane];
    #pragma unroll
    for (int s = 16; s > 0; s >>= 1) {
        int v2 = __shfl_down_sync(0xffffffffu, v, s);
        int i2 = __shfl_down_sync(0xffffffffu, i, s);
        if (v2 > v || (v2 == v && i2 < i)) { v = v2; i = i2; }
    }
    if (lane == 0) {
        g_pk[bc]   = i;
        g_vmax[bc] = (unsigned int)v;
    }
}

// ---------------------------------------------------------------------------
// K4: inlier test per point, accumulate z_sum / n_inl per (b, c)
// ---------------------------------------------------------------------------
__global__ void hn_inlier_kernel() {
    __shared__ float s_z[HN_BC];
    __shared__ float s_n[HN_BC];
    for (int i = threadIdx.x; i < HN_BC; i += blockDim.x) { s_z[i] = 0.0f; s_n[i] = 0.0f; }
    __syncthreads();

    int g = blockIdx.x * blockDim.x + threadIdx.x;
    if (g < HN_B * HN_P) {
        int b = g / HN_P;
        int p = g % HN_P;
        int idx = p * HN_SKIP;
        float xs = (float)(idx % HN_W);
        float ys = (float)(idx / HN_W);

        float4 pt = g_pts[g];
        int label = __float_as_int(pt.w);
        if (label > 0) {
            int pk = g_pk[b * HN_C + label];
            float pkx = (float)(pk % HN_W);
            float pky = (float)(pk / HN_W);
            float ddx = __fsub_rn(pkx, xs);
            float ddy = __fsub_rn(pky, ys);
            float nrm = __fadd_rn(__fsqrt_rn(__fadd_rn(__fmul_rn(ddx, ddx),
                                                       __fmul_rn(ddy, ddy))), 1e-9f);
            float dvx = __fdiv_rn(ddx, nrm);
            float dvy = __fdiv_rn(ddy, nrm);
            float dot = __fadd_rn(__fmul_rn(pt.x, dvx), __fmul_rn(pt.y, dvy));
            if (dot > 0.9f) {
                atomicAdd(&s_z[b * HN_C + label], pt.z);
                atomicAdd(&s_n[b * HN_C + label], 1.0f);
            }
        }
    }
    __syncthreads();
    for (int i = threadIdx.x; i < HN_BC; i += blockDim.x) {
        if (s_n[i] != 0.0f) {
            atomicAdd(&g_zsum[i], s_z[i]);
            atomicAdd(&g_ninl[i], s_n[i]);
        }
    }
}

// ---------------------------------------------------------------------------
// K5: finalize — rois + pose per (b, c)
// ---------------------------------------------------------------------------
__global__ void hn_finalize_kernel(const float* __restrict__ extents,
                                   const float* __restrict__ meta,
                                   float* __restrict__ out) {
    int i = threadIdx.x;
    if (i >= HN_BC) return;
    int b = i / HN_C;
    int c = i % HN_C;

    float cnt   = (float)g_counts[i];
    float vmask = (cnt >= 500.0f && c > 0) ? 1.0f : 0.0f;

    int pk = g_pk[i];
    float pkx  = (float)(pk % HN_W);
    float pky  = (float)(pk / HN_W);
    float vmax = (float)g_vmax[i];

    float zs = g_zsum[i];
    float ni = g_ninl[i];
    float depth  = zs / fmaxf(ni, 1.0f);
    float z_safe = (fabsf(depth) > 0.001f) ? depth : 1.0f;

    float fx = meta[b * 48 + 0];
    float fy = meta[b * 48 + 4];
    float e0 = extents[c * 3 + 0], e1 = extents[c * 3 + 1], e2 = extents[c * 3 + 2];
    float diam = sqrtf(e0 * e0 + e1 * e1 + e2 * e2);
    float half_w = 0.5f * diam * fx / z_safe;
    float half_h = 0.5f * diam * fy / z_safe;

    float* o = out + (size_t)i * 14;
    o[0] = (float)b * vmask;
    o[1] = (float)c * vmask;
    o[2] = (pkx - half_w) * vmask;
    o[3] = (pky - half_h) * vmask;
    o[4] = (pkx + half_w) * vmask;
    o[5] = (pky + half_h) * vmask;
    o[6] = vmax * vmask;
    o[7] = vmask;          // quat = (1,0,0,0) * vmask
    o[8] = 0.0f;
    o[9] = 0.0f;
    o[10] = 0.0f;
    const float* K = meta + b * 48 + 9;   // Kinv row-major 3x3
    #pragma unroll
    for (int j = 0; j < 3; j++) {
        float ray = K[j * 3 + 0] * pkx + K[j * 3 + 1] * pky + K[j * 3 + 2];
        o[11 + j] = depth * ray * vmask;
    }
}

// ---------------------------------------------------------------------------
extern "C" void kernel_launch(void* const* d_in, const int* in_sizes, int n_in,
                              void* d_out, int out_size) {
    const int*   label   = (const int*)d_in[0];
    const float* vp      = (const float*)d_in[1];
    const float* extents = (const float*)d_in[2];
    // d_in[3] = poses (unused by reference)
    const float* meta    = (const float*)d_in[4];
    float* out = (float*)d_out;

    // K0: zero accumulators
    {
        int n4 = (int)(HN_HOUGH_N / 4);
        int blocks = (n4 + 255) / 256;
        hn_zero_kernel<<<blocks, 256>>>();
    }
    // K1: vote (one warp per point)
    {
        int warps = HN_B * HN_P;
        int blocks = (warps * 32 + 255) / 256;
        hn_vote_kernel<<<blocks, 256>>>(label, vp);
    }
    // K2: label histogram
    hn_counts_kernel<<<240, 256>>>(label);
    // K3: argmax per (b,c) — two-pass
    hn_argmax1_kernel<<<HN_BC * HN_SPLIT, 256>>>();
    hn_argmax2_kernel<<<HN_BC, 32>>>();
    // K4: inlier accumulation
    {
        int blocks = (HN_B * HN_P + 255) / 256;
        hn_inlier_kernel<<<blocks, 256>>>();
    }
    // K5: finalize
    hn_finalize_kernel<<<1, 64>>>(extents, meta, out);
}

// round 3
// speedup vs baseline: 1.8087x; 1.2901x over previous
#include <cuda_runtime.h>

#define HN_B      2
#define HN_H      480
#define HN_W      640
#define HN_C      22
#define HN_HW     (HN_H * HN_W)          // 307200
#define HN_SKIP   20
#define HN_P      (HN_HW / HN_SKIP)      // 15360
#define HN_NSTEPS 200
#define HN_BC     (HN_B * HN_C)          // 44

#define HN_PLANE4   (HN_HW / 4)          // 76800 uint4 per plane
#define HN_ZBLOCKS  (HN_PLANE4 / 256)    // 300 blocks per plane (zero)
#define HN_AM_PT    12                   // uint4 per thread (argmax)
#define HN_AM_TILE  (256 * HN_AM_PT)     // 3072 uint4 per block
#define HN_AM_BPP   (HN_PLANE4 / HN_AM_TILE) // 25 blocks per plane
#define HN_NVPL     42                   // voted planes (skip c==0)
#define HN_HISTBLK  600                  // blocks doing label histogram in vote kernel

// Scratch (device globals; zero-initialized at module load)
__device__ unsigned int       g_hough[HN_B * HN_C * HN_HW];
__device__ float4             g_pts[HN_B * HN_P];   // dnx, dny, z, label(bits)
__device__ unsigned long long g_vkey[HN_BC];        // (vmax<<32) | ~pk
__device__ float              g_zsum[HN_BC];
__device__ float              g_ninl[HN_BC];
__device__ unsigned int       g_counts[HN_BC];

// map voted-plane index j in [0,42) -> bc, skipping bc==0 and bc==22
__device__ __forceinline__ int hn_plane(int j) { return (j < 21) ? (j + 1) : (j + 2); }

// ---------------------------------------------------------------------------
// K0: zero the 42 voted hough planes (1 uint4 store / thread) + small arrays
// ---------------------------------------------------------------------------
__global__ void hn_zero_kernel() {
    int bc  = hn_plane(blockIdx.y);
    int off = blockIdx.x * 256 + threadIdx.x;           // < 76800
    reinterpret_cast<uint4*>(g_hough)[(size_t)bc * HN_PLANE4 + off] =
        make_uint4(0u, 0u, 0u, 0u);
    if (blockIdx.x == 0 && blockIdx.y == 0 && threadIdx.x < HN_BC) {
        g_vkey[threadIdx.x]   = 0ull;
        g_zsum[threadIdx.x]   = 0.0f;
        g_ninl[threadIdx.x]   = 0.0f;
        g_counts[threadIdx.x] = 0u;
    }
}

// ---------------------------------------------------------------------------
// K1: hough voting (one warp per point) + fused full-image label histogram
// ---------------------------------------------------------------------------
__global__ void hn_vote_kernel(const int* __restrict__ label_2d,
                               const float* __restrict__ vertex_pred) {
    __shared__ unsigned int s_cnt[HN_BC];
    bool do_hist = (blockIdx.x < HN_HISTBLK);
    if (do_hist) {
        for (int i = threadIdx.x; i < HN_BC; i += 256) s_cnt[i] = 0u;
        __syncthreads();
        // 153600 int4 loads cover 614400 labels; 600 blocks x 256 threads
        int g4 = blockIdx.x * 256 + threadIdx.x;        // < 153600
        int4 l4 = reinterpret_cast<const int4*>(label_2d)[g4];
        int b = (g4 * 4) / HN_HW;                       // 4 labels share batch (HW%4==0)
        atomicAdd(&s_cnt[b * HN_C + l4.x], 1u);
        atomicAdd(&s_cnt[b * HN_C + l4.y], 1u);
        atomicAdd(&s_cnt[b * HN_C + l4.z], 1u);
        atomicAdd(&s_cnt[b * HN_C + l4.w], 1u);
    }

    // ---- voting ----
    int gwarp = (blockIdx.x * 256 + threadIdx.x) >> 5;
    int lane  = threadIdx.x & 31;
    if (gwarp < HN_B * HN_P) {
        int b = gwarp / HN_P;
        int p = gwarp % HN_P;
        int idx = p * HN_SKIP;
        float xs = (float)(idx % HN_W);
        float ys = (float)(idx / HN_W);

        int label = label_2d[b * HN_HW + idx];
        const float* vp = vertex_pred + ((size_t)(b * HN_HW + idx)) * (3 * HN_C) + label * 3;
        float dx = vp[0], dy = vp[1], z = vp[2];

        float nrm = __fadd_rn(__fsqrt_rn(__fadd_rn(__fmul_rn(dx, dx), __fmul_rn(dy, dy))), 1e-9f);
        float dnx = __fdiv_rn(dx, nrm);
        float dny = __fdiv_rn(dy, nrm);

        if (lane == 0) {
            float4 pt;
            pt.x = dnx; pt.y = dny; pt.z = z; pt.w = __int_as_float(label);
            g_pts[gwarp] = pt;
        }

        if (label > 0) {
            unsigned int* hbase = g_hough + (size_t)(b * HN_C + label) * HN_HW;
            #pragma unroll 7
            for (int i = lane; i < HN_NSTEPS; i += 32) {
                float t  = (float)(i + 1) * 4.0f;
                float cx = __fadd_rn(xs, __fmul_rn(dnx, t));
                float cy = __fadd_rn(ys, __fmul_rn(dny, t));
                int cxi = (int)rintf(cx);               // round-half-even == jnp.round
                int cyi = (int)rintf(cy);
                if (cxi >= 0 && cxi < HN_W && cyi >= 0 && cyi < HN_H)
                    atomicAdd(&hbase[cyi * HN_W + cxi], 1u);
            }
        }
    }

    if (do_hist) {
        __syncthreads();
        for (int i = threadIdx.x; i < HN_BC; i += 256)
            if (s_cnt[i]) atomicAdd(&g_counts[i], s_cnt[i]);
    }
}

// ---------------------------------------------------------------------------
// K2: argmax over the 42 voted planes. grid (25, 42), 256 thr.
//     4 independent uint4 loads per unroll batch (MLP=4), ascending scan with
//     strict '>' keeps first index; block reduce on packed key; atomicMax out.
// ---------------------------------------------------------------------------
__global__ void hn_argmax_kernel() {
    int bc = hn_plane(blockIdx.y);
    const uint4* h4 = reinterpret_cast<const uint4*>(g_hough)
                    + (size_t)bc * HN_PLANE4 + blockIdx.x * HN_AM_TILE;
    int ebase = blockIdx.x * HN_AM_TILE * 4;            // element index of block tile

    int bv = -1;
    int bi = 0;
    #pragma unroll
    for (int o = 0; o < HN_AM_PT; o += 4) {
        uint4 r0 = h4[threadIdx.x + (o + 0) * 256];
        uint4 r1 = h4[threadIdx.x + (o + 1) * 256];
        uint4 r2 = h4[threadIdx.x + (o + 2) * 256];
        uint4 r3 = h4[threadIdx.x + (o + 3) * 256];
        int e0 = ebase + (threadIdx.x + (o + 0) * 256) * 4;
        int e1 = ebase + (threadIdx.x + (o + 1) * 256) * 4;
        int e2 = ebase + (threadIdx.x + (o + 2) * 256) * 4;
        int e3 = ebase + (threadIdx.x + (o + 3) * 256) * 4;
        if ((int)r0.x > bv) { bv = (int)r0.x; bi = e0; }
        if ((int)r0.y > bv) { bv = (int)r0.y; bi = e0 + 1; }
        if ((int)r0.z > bv) { bv = (int)r0.z; bi = e0 + 2; }
        if ((int)r0.w > bv) { bv = (int)r0.w; bi = e0 + 3; }
        if ((int)r1.x > bv) { bv = (int)r1.x; bi = e1; }
        if ((int)r1.y > bv) { bv = (int)r1.y; bi = e1 + 1; }
        if ((int)r1.z > bv) { bv = (int)r1.z; bi = e1 + 2; }
        if ((int)r1.w > bv) { bv = (int)r1.w; bi = e1 + 3; }
        if ((int)r2.x > bv) { bv = (int)r2.x; bi = e2; }
        if ((int)r2.y > bv) { bv = (int)r2.y; bi = e2 + 1; }
        if ((int)r2.z > bv) { bv = (int)r2.z; bi = e2 + 2; }
        if ((int)r2.w > bv) { bv = (int)r2.w; bi = e2 + 3; }
        if ((int)r3.x > bv) { bv = (int)r3.x; bi = e3; }
        if ((int)r3.y > bv) { bv = (int)r3.y; bi = e3 + 1; }
        if ((int)r3.z > bv) { bv = (int)r3.z; bi = e3 + 2; }
        if ((int)r3.w > bv) { bv = (int)r3.w; bi = e3 + 3; }
    }

    // packed key: value in high 32, ~index in low 32 (bigger ~idx == smaller idx)
    unsigned long long key = ((unsigned long long)(unsigned)bv << 32)
                           | (unsigned)(~bi);

    __shared__ unsigned long long sk[256];
    sk[threadIdx.x] = key;
    __syncthreads();
    #pragma unroll
    for (int s = 128; s > 0; s >>= 1) {
        if (threadIdx.x < s) {
            unsigned long long o = sk[threadIdx.x + s];
            if (o > sk[threadIdx.x]) sk[threadIdx.x] = o;
        }
        __syncthreads();
    }
    if (threadIdx.x == 0)
        atomicMax(&g_vkey[bc], sk[0]);
}

// ---------------------------------------------------------------------------
// K3: inlier test per point, accumulate z_sum / n_inl per (b, c)
// ---------------------------------------------------------------------------
__global__ void hn_inlier_kernel() {
    __shared__ float s_z[HN_BC];
    __shared__ float s_n[HN_BC];
    for (int i = threadIdx.x; i < HN_BC; i += blockDim.x) { s_z[i] = 0.0f; s_n[i] = 0.0f; }
    __syncthreads();

    int g = blockIdx.x * blockDim.x + threadIdx.x;
    if (g < HN_B * HN_P) {
        int b = g / HN_P;
        int p = g % HN_P;
        int idx = p * HN_SKIP;
        float xs = (float)(idx % HN_W);
        float ys = (float)(idx / HN_W);

        float4 pt = g_pts[g];
        int label = __float_as_int(pt.w);
        if (label > 0) {
            int pk = (int)(~(unsigned)g_vkey[b * HN_C + label]);
            float pkx = (float)(pk % HN_W);
            float pky = (float)(pk / HN_W);
            float ddx = __fsub_rn(pkx, xs);
            float ddy = __fsub_rn(pky, ys);
            float nrm = __fadd_rn(__fsqrt_rn(__fadd_rn(__fmul_rn(ddx, ddx),
                                                       __fmul_rn(ddy, ddy))), 1e-9f);
            float dvx = __fdiv_rn(ddx, nrm);
            float dvy = __fdiv_rn(ddy, nrm);
            float dot = __fadd_rn(__fmul_rn(pt.x, dvx), __fmul_rn(pt.y, dvy));
            if (dot > 0.9f) {
                atomicAdd(&s_z[b * HN_C + label], pt.z);
                atomicAdd(&s_n[b * HN_C + label], 1.0f);
            }
        }
    }
    __syncthreads();
    for (int i = threadIdx.x; i < HN_BC; i += blockDim.x) {
        if (s_n[i] != 0.0f) {
            atomicAdd(&g_zsum[i], s_z[i]);
            atomicAdd(&g_ninl[i], s_n[i]);
        }
    }
}

// ---------------------------------------------------------------------------
// K4: finalize — rois + pose per (b, c)
// ---------------------------------------------------------------------------
__global__ void hn_finalize_kernel(const float* __restrict__ extents,
                                   const float* __restrict__ meta,
                                   float* __restrict__ out) {
    int i = threadIdx.x;
    if (i >= HN_BC) return;
    int b = i / HN_C;
    int c = i % HN_C;

    float cnt   = (float)g_counts[i];
    float vmask = (cnt >= 500.0f && c > 0) ? 1.0f : 0.0f;

    unsigned long long key = g_vkey[i];
    int pk = (int)(~(unsigned)key);
    // skipped planes (c==0) keep key 0 -> pk garbage; fully masked, keep finite
    if (c == 0) pk = 0;
    float pkx  = (float)(pk % HN_W);
    float pky  = (float)(pk / HN_W);
    float vmax = (float)(unsigned)(key >> 32);

    float zs = g_zsum[i];
    float ni = g_ninl[i];
    float depth  = zs / fmaxf(ni, 1.0f);
    float z_safe = (fabsf(depth) > 0.001f) ? depth : 1.0f;

    float fx = meta[b * 48 + 0];
    float fy = meta[b * 48 + 4];
    float e0 = extents[c * 3 + 0], e1 = extents[c * 3 + 1], e2 = extents[c * 3 + 2];
    float diam = sqrtf(e0 * e0 + e1 * e1 + e2 * e2);
    float half_w = 0.5f * diam * fx / z_safe;
    float half_h = 0.5f * diam * fy / z_safe;

    float* o = out + (size_t)i * 14;
    o[0] = (float)b * vmask;
    o[1] = (float)c * vmask;
    o[2] = (pkx - half_w) * vmask;
    o[3] = (pky - half_h) * vmask;
    o[4] = (pkx + half_w) * vmask;
    o[5] = (pky + half_h) * vmask;
    o[6] = vmax * vmask;
    o[7] = vmask;          // quat = (1,0,0,0) * vmask
    o[8] = 0.0f;
    o[9] = 0.0f;
    o[10] = 0.0f;
    const float* K = meta + b * 48 + 9;   // Kinv row-major 3x3
    #pragma unroll
    for (int j = 0; j < 3; j++) {
        float ray = K[j * 3 + 0] * pkx + K[j * 3 + 1] * pky + K[j * 3 + 2];
        o[11 + j] = depth * ray * vmask;
    }
}

// ---------------------------------------------------------------------------
extern "C" void kernel_launch(void* const* d_in, const int* in_sizes, int n_in,
                              void* d_out, int out_size) {
    const int*   label   = (const int*)d_in[0];
    const float* vp      = (const float*)d_in[1];
    const float* extents = (const float*)d_in[2];
    // d_in[3] = poses (unused by reference)
    const float* meta    = (const float*)d_in[4];
    float* out = (float*)d_out;

    // K0: zero 42 voted planes + small accumulators
    {
        dim3 grid(HN_ZBLOCKS, HN_NVPL);
        hn_zero_kernel<<<grid, 256>>>();
    }
    // K1: vote (one warp per point) + fused label histogram
    {
        int blocks = (HN_B * HN_P * 32 + 255) / 256;    // 3840 >= HN_HISTBLK
        hn_vote_kernel<<<blocks, 256>>>(label, vp);
    }
    // K2: argmax per voted plane (single pass, atomicMax on packed key)
    {
        dim3 grid(HN_AM_BPP, HN_NVPL);
        hn_argmax_kernel<<<grid, 256>>>();
    }
    // K3: inlier accumulation
    {
        int blocks = (HN_B * HN_P + 255) / 256;
        hn_inlier_kernel<<<blocks, 256>>>();
    }
    // K4: finalize
    hn_finalize_kernel<<<1, 64>>>(extents, meta, out);
}

// round 4
// speedup vs baseline: 2.0738x; 1.1466x over previous
#include <cuda_runtime.h>

#define HN_B      2
#define HN_H      480
#define HN_W      640
#define HN_C      22
#define HN_HW     (HN_H * HN_W)          // 307200
#define HN_SKIP   20
#define HN_P      (HN_HW / HN_SKIP)      // 15360
#define HN_NSTEPS 200
#define HN_BC     (HN_B * HN_C)          // 44

#define HN_PLANEW  (HN_HW / 2)           // 153600 uint32 words (2 px each)
#define HN_PLANE4  (HN_HW / 8)           // 38400 uint4 per plane
#define HN_AM_PT   6                     // uint4 per thread (argmax)
#define HN_AM_TILE (256 * HN_AM_PT)      // 1536 uint4 per block
#define HN_AM_BPP  (HN_PLANE4 / HN_AM_TILE) // 25 blocks per plane
#define HN_NVPL    42                    // voted planes (skip c==0)
#define HN_HISTBLK 600                   // vote-kernel blocks that also do the histogram
#define HN_INLBLK  ((HN_B * HN_P + 255) / 256)  // 120

// Scratch (device globals; zero-initialized at module load; every kernel_launch
// restores them to zero, so graph replays are deterministic)
__device__ unsigned int       g_hough[HN_B * HN_C * HN_PLANEW];  // uint16 bins, packed
__device__ float4             g_pts[HN_B * HN_P];   // dnx, dny, z, label(bits)
__device__ unsigned long long g_vkey[HN_BC];        // (vmax<<32) | ~pk
__device__ float              g_zsum[HN_BC];
__device__ float              g_ninl[HN_BC];
__device__ unsigned int       g_counts[HN_BC];
__device__ unsigned int       g_ticket;

// map voted-plane index j in [0,42) -> bc, skipping bc==0 and bc==22
__device__ __forceinline__ int hn_plane(int j) { return (j < 21) ? (j + 1) : (j + 2); }

// ---------------------------------------------------------------------------
// K1: hough voting (one warp per point) + fused full-image label histogram
// ---------------------------------------------------------------------------
__global__ void hn_vote_kernel(const int* __restrict__ label_2d,
                               const float* __restrict__ vertex_pred) {
    __shared__ unsigned int s_cnt[HN_BC];
    bool do_hist = (blockIdx.x < HN_HISTBLK);
    if (do_hist) {
        for (int i = threadIdx.x; i < HN_BC; i += 256) s_cnt[i] = 0u;
        __syncthreads();
        // 153600 int4 loads cover 614400 labels; 600 blocks x 256 threads
        int g4 = blockIdx.x * 256 + threadIdx.x;        // < 153600
        int4 l4 = reinterpret_cast<const int4*>(label_2d)[g4];
        int b = (g4 * 4) / HN_HW;                       // 4 labels share batch (HW%4==0)
        atomicAdd(&s_cnt[b * HN_C + l4.x], 1u);
        atomicAdd(&s_cnt[b * HN_C + l4.y], 1u);
        atomicAdd(&s_cnt[b * HN_C + l4.z], 1u);
        atomicAdd(&s_cnt[b * HN_C + l4.w], 1u);
    }

    // ---- voting ----
    int gwarp = (blockIdx.x * 256 + threadIdx.x) >> 5;
    int lane  = threadIdx.x & 31;
    if (gwarp < HN_B * HN_P) {
        int b = gwarp / HN_P;
        int p = gwarp % HN_P;
        int idx = p * HN_SKIP;
        float xs = (float)(idx % HN_W);
        float ys = (float)(idx / HN_W);

        int label = label_2d[b * HN_HW + idx];
        const float* vp = vertex_pred + ((size_t)(b * HN_HW + idx)) * (3 * HN_C) + label * 3;
        float dx = vp[0], dy = vp[1], z = vp[2];

        float nrm = __fadd_rn(__fsqrt_rn(__fadd_rn(__fmul_rn(dx, dx), __fmul_rn(dy, dy))), 1e-9f);
        float dnx = __fdiv_rn(dx, nrm);
        float dny = __fdiv_rn(dy, nrm);

        if (lane == 0) {
            float4 pt;
            pt.x = dnx; pt.y = dny; pt.z = z; pt.w = __int_as_float(label);
            g_pts[gwarp] = pt;
        }

        if (label > 0) {
            unsigned int* hbase = g_hough + (size_t)(b * HN_C + label) * HN_PLANEW;
            #pragma unroll 7
            for (int i = lane; i < HN_NSTEPS; i += 32) {
                float t  = (float)(i + 1) * 4.0f;
                float cx = __fadd_rn(xs, __fmul_rn(dnx, t));
                float cy = __fadd_rn(ys, __fmul_rn(dny, t));
                int cxi = (int)rintf(cx);               // round-half-even == jnp.round
                int cyi = (int)rintf(cy);
                if (cxi >= 0 && cxi < HN_W && cyi >= 0 && cyi < HN_H) {
                    // packed uint16 bins: 2 px per word; low-half overflow is
                    // impossible (max votes per bin <= points per label < 65536)
                    atomicAdd(&hbase[cyi * (HN_W / 2) + (cxi >> 1)],
                              1u << ((cxi & 1) * 16));
                }
            }
        }
    }

    if (do_hist) {
        __syncthreads();
        for (int i = threadIdx.x; i < HN_BC; i += 256)
            if (s_cnt[i]) atomicAdd(&g_counts[i], s_cnt[i]);
    }
}

// ---------------------------------------------------------------------------
// K2: argmax over the 42 voted planes + write-behind clear for next replay.
//     grid (25, 42), 256 thr. 6 independent uint4 loads per thread (MLP=6),
//     ascending scan, strict '>' keeps first index; block reduce on packed
//     key (val<<32 | ~idx); atomicMax into g_vkey.
// ---------------------------------------------------------------------------
__global__ void hn_argmax_kernel() {
    int bc = hn_plane(blockIdx.y);
    uint4* h4 = reinterpret_cast<uint4*>(g_hough)
              + (size_t)bc * HN_PLANE4 + blockIdx.x * HN_AM_TILE;
    int ebase = blockIdx.x * HN_AM_TILE * 8;            // pixel index of block tile

    uint4 r[HN_AM_PT];
    #pragma unroll
    for (int o = 0; o < HN_AM_PT; o++)
        r[o] = h4[threadIdx.x + o * 256];               // all loads in flight

    int bv = -1;
    int bi = 0;
    #pragma unroll
    for (int o = 0; o < HN_AM_PT; o++) {
        int e = ebase + (threadIdx.x + o * 256) * 8;
        unsigned int w;
        w = r[o].x;
        if ((int)(w & 0xffffu) > bv) { bv = (int)(w & 0xffffu); bi = e; }
        if ((int)(w >> 16)     > bv) { bv = (int)(w >> 16);     bi = e + 1; }
        w = r[o].y;
        if ((int)(w & 0xffffu) > bv) { bv = (int)(w & 0xffffu); bi = e + 2; }
        if ((int)(w >> 16)     > bv) { bv = (int)(w >> 16);     bi = e + 3; }
        w = r[o].z;
        if ((int)(w & 0xffffu) > bv) { bv = (int)(w & 0xffffu); bi = e + 4; }
        if ((int)(w >> 16)     > bv) { bv = (int)(w >> 16);     bi = e + 5; }
        w = r[o].w;
        if ((int)(w & 0xffffu) > bv) { bv = (int)(w & 0xffffu); bi = e + 6; }
        if ((int)(w >> 16)     > bv) { bv = (int)(w >> 16);     bi = e + 7; }
    }

    // clear tile for the next run (write-behind)
    uint4 z4 = make_uint4(0u, 0u, 0u, 0u);
    #pragma unroll
    for (int o = 0; o < HN_AM_PT; o++)
        h4[threadIdx.x + o * 256] = z4;

    unsigned long long key = ((unsigned long long)(unsigned)bv << 32)
                           | (unsigned)(~bi);

    __shared__ unsigned long long sk[256];
    sk[threadIdx.x] = key;
    __syncthreads();
    #pragma unroll
    for (int s = 128; s > 0; s >>= 1) {
        if (threadIdx.x < s) {
            unsigned long long o = sk[threadIdx.x + s];
            if (o > sk[threadIdx.x]) sk[threadIdx.x] = o;
        }
        __syncthreads();
    }
    if (threadIdx.x == 0)
        atomicMax(&g_vkey[bc], sk[0]);
}

// ---------------------------------------------------------------------------
// K3: inlier accumulation + fused finalize in the last block (ticket pattern).
//     The last block also resets all small accumulators for the next replay.
// ---------------------------------------------------------------------------
__global__ void hn_inlier_kernel(const float* __restrict__ extents,
                                 const float* __restrict__ meta,
                                 float* __restrict__ out) {
    __shared__ float s_z[HN_BC];
    __shared__ float s_n[HN_BC];
    __shared__ bool  s_last;
    for (int i = threadIdx.x; i < HN_BC; i += 256) { s_z[i] = 0.0f; s_n[i] = 0.0f; }
    __syncthreads();

    int g = blockIdx.x * 256 + threadIdx.x;
    if (g < HN_B * HN_P) {
        int b = g / HN_P;
        int p = g % HN_P;
        int idx = p * HN_SKIP;
        float xs = (float)(idx % HN_W);
        float ys = (float)(idx / HN_W);

        float4 pt = g_pts[g];
        int label = __float_as_int(pt.w);
        if (label > 0) {
            int pk = (int)(~(unsigned)g_vkey[b * HN_C + label]);
            float pkx = (float)(pk % HN_W);
            float pky = (float)(pk / HN_W);
            float ddx = __fsub_rn(pkx, xs);
            float ddy = __fsub_rn(pky, ys);
            float nrm = __fadd_rn(__fsqrt_rn(__fadd_rn(__fmul_rn(ddx, ddx),
                                                       __fmul_rn(ddy, ddy))), 1e-9f);
            float dvx = __fdiv_rn(ddx, nrm);
            float dvy = __fdiv_rn(ddy, nrm);
            float dot = __fadd_rn(__fmul_rn(pt.x, dvx), __fmul_rn(pt.y, dvy));
            if (dot > 0.9f) {
                atomicAdd(&s_z[b * HN_C + label], pt.z);
                atomicAdd(&s_n[b * HN_C + label], 1.0f);
            }
        }
    }
    __syncthreads();
    for (int i = threadIdx.x; i < HN_BC; i += 256) {
        if (s_n[i] != 0.0f) {
            atomicAdd(&g_zsum[i], s_z[i]);
            atomicAdd(&g_ninl[i], s_n[i]);
        }
    }

    // ---- last-block finalize ----
    __threadfence();
    __syncthreads();
    if (threadIdx.x == 0)
        s_last = (atomicAdd(&g_ticket, 1u) == (unsigned)(gridDim.x - 1));
    __syncthreads();
    if (!s_last) return;

    int i = threadIdx.x;
    if (i < HN_BC) {
        int b = i / HN_C;
        int c = i % HN_C;

        float cnt   = (float)(*(volatile unsigned int*)&g_counts[i]);
        float vmask = (cnt >= 500.0f && c > 0) ? 1.0f : 0.0f;

        unsigned long long key = *(volatile unsigned long long*)&g_vkey[i];
        int pk = (c == 0) ? 0 : (int)(~(unsigned)key);
        float pkx  = (float)(pk % HN_W);
        float pky  = (float)(pk / HN_W);
        float vmax = (float)(unsigned)(key >> 32);

        float zs = *(volatile float*)&g_zsum[i];
        float ni = *(volatile float*)&g_ninl[i];
        float depth  = zs / fmaxf(ni, 1.0f);
        float z_safe = (fabsf(depth) > 0.001f) ? depth : 1.0f;

        float fx = meta[b * 48 + 0];
        float fy = meta[b * 48 + 4];
        float e0 = extents[c * 3 + 0], e1 = extents[c * 3 + 1], e2 = extents[c * 3 + 2];
        float diam = sqrtf(e0 * e0 + e1 * e1 + e2 * e2);
        float half_w = 0.5f * diam * fx / z_safe;
        float half_h = 0.5f * diam * fy / z_safe;

        float* o = out + (size_t)i * 14;
        o[0] = (float)b * vmask;
        o[1] = (float)c * vmask;
        o[2] = (pkx - half_w) * vmask;
        o[3] = (pky - half_h) * vmask;
        o[4] = (pkx + half_w) * vmask;
        o[5] = (pky + half_h) * vmask;
        o[6] = vmax * vmask;
        o[7] = vmask;          // quat = (1,0,0,0) * vmask
        o[8] = 0.0f;
        o[9] = 0.0f;
        o[10] = 0.0f;
        const float* K = meta + b * 48 + 9;   // Kinv row-major 3x3
        #pragma unroll
        for (int j = 0; j < 3; j++) {
            float ray = K[j * 3 + 0] * pkx + K[j * 3 + 1] * pky + K[j * 3 + 2];
            o[11 + j] = depth * ray * vmask;
        }

        // reset accumulators for the next graph replay
        g_vkey[i]   = 0ull;
        g_zsum[i]   = 0.0f;
        g_ninl[i]   = 0.0f;
        g_counts[i] = 0u;
    }
    if (threadIdx.x == 0) g_ticket = 0u;
}

// ---------------------------------------------------------------------------
extern "C" void kernel_launch(void* const* d_in, const int* in_sizes, int n_in,
                              void* d_out, int out_size) {
    const int*   label   = (const int*)d_in[0];
    const float* vp      = (const float*)d_in[1];
    const float* extents = (const float*)d_in[2];
    // d_in[3] = poses (unused by reference)
    const float* meta    = (const float*)d_in[4];
    float* out = (float*)d_out;

    // K1: vote (one warp per point) + fused label histogram
    {
        int blocks = (HN_B * HN_P * 32 + 255) / 256;    // 3840 >= HN_HISTBLK
        hn_vote_kernel<<<blocks, 256>>>(label, vp);
    }
    // K2: argmax per voted plane + write-behind clear
    {
        dim3 grid(HN_AM_BPP, HN_NVPL);
        hn_argmax_kernel<<<grid, 256>>>();
    }
    // K3: inlier accumulation + last-block finalize
    hn_inlier_kernel<<<HN_INLBLK, 256>>>(extents, meta, out);
}

// round 5
// speedup vs baseline: 2.1201x; 1.0223x over previous
#include <cuda_runtime.h>

#define HN_B      2
#define HN_H      480
#define HN_W      640
#define HN_C      22
#define HN_HW     (HN_H * HN_W)          // 307200
#define HN_SKIP   20
#define HN_P      (HN_HW / HN_SKIP)      // 15360
#define HN_NSTEPS 200
#define HN_BC     (HN_B * HN_C)          // 44

#define HN_PLANEW  (HN_HW / 2)           // 153600 uint32 words (2 px each)
#define HN_PLANE4  (HN_HW / 8)           // 38400 uint4 per plane
#define HN_AM_PT   6                     // uint4 per thread (argmax)
#define HN_AM_TILE (256 * HN_AM_PT)      // 1536 uint4 per block
#define HN_AM_BPP  (HN_PLANE4 / HN_AM_TILE) // 25 blocks per plane
#define HN_NVPL    42                    // voted planes (skip c==0)
#define HN_HISTBLK 600                   // vote-kernel blocks that also do the histogram
#define HN_INLBLK  ((HN_B * HN_P + 255) / 256)  // 120

// Scratch (device globals; zero-initialized at module load; every kernel_launch
// restores them to zero, so graph replays are deterministic)
__device__ unsigned int       g_hough[HN_B * HN_C * HN_PLANEW];  // uint16 bins, packed
__device__ float4             g_pts[HN_B * HN_P];   // dnx, dny, z, label(bits)
__device__ unsigned long long g_vkey[HN_BC];        // (vmax<<32) | ~pk
__device__ float              g_zsum[HN_BC];
__device__ float              g_ninl[HN_BC];
__device__ unsigned int       g_counts[HN_BC];
__device__ unsigned int       g_ticket;

// map voted-plane index j in [0,42) -> bc, skipping bc==0 and bc==22
__device__ __forceinline__ int hn_plane(int j) { return (j < 21) ? (j + 1) : (j + 2); }

// ---------------------------------------------------------------------------
// K1: hough voting (one warp per point) + fused full-image label histogram.
//     Rays exit the image monotonically, so the step loop is bounded by a
//     conservative exit parameter; the exact per-step bounds check remains.
// ---------------------------------------------------------------------------
__global__ void hn_vote_kernel(const int* __restrict__ label_2d,
                               const float* __restrict__ vertex_pred) {
    __shared__ unsigned int s_cnt[HN_BC];
    bool do_hist = (blockIdx.x < HN_HISTBLK);
    if (do_hist) {
        for (int i = threadIdx.x; i < HN_BC; i += 256) s_cnt[i] = 0u;
        __syncthreads();
        // 153600 int4 loads cover 614400 labels; 600 blocks x 256 threads
        int g4 = blockIdx.x * 256 + threadIdx.x;        // < 153600
        int4 l4 = reinterpret_cast<const int4*>(label_2d)[g4];
        int b = (g4 * 4) / HN_HW;                       // 4 labels share batch (HW%4==0)
        atomicAdd(&s_cnt[b * HN_C + l4.x], 1u);
        atomicAdd(&s_cnt[b * HN_C + l4.y], 1u);
        atomicAdd(&s_cnt[b * HN_C + l4.z], 1u);
        atomicAdd(&s_cnt[b * HN_C + l4.w], 1u);
    }

    // ---- voting ----
    int gwarp = (blockIdx.x * 256 + threadIdx.x) >> 5;
    int lane  = threadIdx.x & 31;
    if (gwarp < HN_B * HN_P) {
        int b = gwarp / HN_P;
        int p = gwarp % HN_P;
        int idx = p * HN_SKIP;
        float xs = (float)(idx % HN_W);
        float ys = (float)(idx / HN_W);

        int label = label_2d[b * HN_HW + idx];
        const float* vp = vertex_pred + ((size_t)(b * HN_HW + idx)) * (3 * HN_C) + label * 3;
        float dx = vp[0], dy = vp[1], z = vp[2];

        float nrm = __fadd_rn(__fsqrt_rn(__fadd_rn(__fmul_rn(dx, dx), __fmul_rn(dy, dy))), 1e-9f);
        float dnx = __fdiv_rn(dx, nrm);
        float dny = __fdiv_rn(dy, nrm);

        if (lane == 0) {
            float4 pt;
            pt.x = dnx; pt.y = dny; pt.z = z; pt.w = __int_as_float(label);
            g_pts[gwarp] = pt;
        }

        if (label > 0) {
            // conservative ray-exit bound (per-step check stays authoritative):
            // in-bounds after round-half-even needs cx in [-0.5, 639.5),
            // cy in [-0.5, 479.5); use +-0.6 margin.
            float tx = (dnx > 0.0f) ? (639.6f - xs) / dnx
                     : (dnx < 0.0f) ? (-0.6f - xs) / dnx : 1e9f;
            float ty = (dny > 0.0f) ? (479.6f - ys) / dny
                     : (dny < 0.0f) ? (-0.6f - ys) / dny : 1e9f;
            float thi = fminf(fminf(tx, ty), 800.0f);
            int nb = (int)(thi * 0.25f) + 1;            // steps t=(i+1)*4 <= thi (+slack)
            if (nb > HN_NSTEPS) nb = HN_NSTEPS;

            unsigned int* hbase = g_hough + (size_t)(b * HN_C + label) * HN_PLANEW;
            #pragma unroll 2
            for (int i = lane; i < nb; i += 32) {
                float t  = (float)(i + 1) * 4.0f;
                float cx = __fadd_rn(xs, __fmul_rn(dnx, t));
                float cy = __fadd_rn(ys, __fmul_rn(dny, t));
                int cxi = __float2int_rn(cx);           // round-half-even == jnp.round
                int cyi = __float2int_rn(cy);
                if (cxi >= 0 && cxi < HN_W && cyi >= 0 && cyi < HN_H) {
                    // packed uint16 bins: 2 px per word; low-half overflow is
                    // impossible (max votes per bin <= points per label < 65536)
                    atomicAdd(&hbase[cyi * (HN_W / 2) + (cxi >> 1)],
                              1u << ((cxi & 1) * 16));
                }
            }
        }
    }

    if (do_hist) {
        __syncthreads();
        for (int i = threadIdx.x; i < HN_BC; i += 256)
            if (s_cnt[i]) atomicAdd(&g_counts[i], s_cnt[i]);
    }
}

// ---------------------------------------------------------------------------
// K2: argmax over the 42 voted planes + write-behind clear for next replay.
//     grid (25, 42), 256 thr. 6 independent uint4 loads per thread (MLP=6),
//     ascending scan, strict '>' keeps first index; block reduce on packed
//     key (val<<32 | ~idx); atomicMax into g_vkey.
// ---------------------------------------------------------------------------
__global__ void hn_argmax_kernel() {
    int bc = hn_plane(blockIdx.y);
    uint4* h4 = reinterpret_cast<uint4*>(g_hough)
              + (size_t)bc * HN_PLANE4 + blockIdx.x * HN_AM_TILE;
    int ebase = blockIdx.x * HN_AM_TILE * 8;            // pixel index of block tile

    uint4 r[HN_AM_PT];
    #pragma unroll
    for (int o = 0; o < HN_AM_PT; o++)
        r[o] = h4[threadIdx.x + o * 256];               // all loads in flight

    int bv = -1;
    int bi = 0;
    #pragma unroll
    for (int o = 0; o < HN_AM_PT; o++) {
        int e = ebase + (threadIdx.x + o * 256) * 8;
        unsigned int w;
        w = r[o].x;
        if ((int)(w & 0xffffu) > bv) { bv = (int)(w & 0xffffu); bi = e; }
        if ((int)(w >> 16)     > bv) { bv = (int)(w >> 16);     bi = e + 1; }
        w = r[o].y;
        if ((int)(w & 0xffffu) > bv) { bv = (int)(w & 0xffffu); bi = e + 2; }
        if ((int)(w >> 16)     > bv) { bv = (int)(w >> 16);     bi = e + 3; }
        w = r[o].z;
        if ((int)(w & 0xffffu) > bv) { bv = (int)(w & 0xffffu); bi = e + 4; }
        if ((int)(w >> 16)     > bv) { bv = (int)(w >> 16);     bi = e + 5; }
        w = r[o].w;
        if ((int)(w & 0xffffu) > bv) { bv = (int)(w & 0xffffu); bi = e + 6; }
        if ((int)(w >> 16)     > bv) { bv = (int)(w >> 16);     bi = e + 7; }
    }

    // clear tile for the next run (write-behind)
    uint4 z4 = make_uint4(0u, 0u, 0u, 0u);
    #pragma unroll
    for (int o = 0; o < HN_AM_PT; o++)
        h4[threadIdx.x + o * 256] = z4;

    unsigned long long key = ((unsigned long long)(unsigned)bv << 32)
                           | (unsigned)(~bi);

    __shared__ unsigned long long sk[256];
    sk[threadIdx.x] = key;
    __syncthreads();
    #pragma unroll
    for (int s = 128; s > 0; s >>= 1) {
        if (threadIdx.x < s) {
            unsigned long long o = sk[threadIdx.x + s];
            if (o > sk[threadIdx.x]) sk[threadIdx.x] = o;
        }
        __syncthreads();
    }
    if (threadIdx.x == 0)
        atomicMax(&g_vkey[bc], sk[0]);
}

// ---------------------------------------------------------------------------
// K3: inlier accumulation + fused finalize in the last block (ticket pattern).
//     The last block also resets all small accumulators for the next replay.
// ---------------------------------------------------------------------------
__global__ void hn_inlier_kernel(const float* __restrict__ extents,
                                 const float* __restrict__ meta,
                                 float* __restrict__ out) {
    __shared__ float s_z[HN_BC];
    __shared__ float s_n[HN_BC];
    __shared__ bool  s_last;
    for (int i = threadIdx.x; i < HN_BC; i += 256) { s_z[i] = 0.0f; s_n[i] = 0.0f; }
    __syncthreads();

    int g = blockIdx.x * 256 + threadIdx.x;
    if (g < HN_B * HN_P) {
        int b = g / HN_P;
        int p = g % HN_P;
        int idx = p * HN_SKIP;
        float xs = (float)(idx % HN_W);
        float ys = (float)(idx / HN_W);

        float4 pt = g_pts[g];
        int label = __float_as_int(pt.w);
        if (label > 0) {
            int pk = (int)(~(unsigned)g_vkey[b * HN_C + label]);
            float pkx = (float)(pk % HN_W);
            float pky = (float)(pk / HN_W);
            float ddx = __fsub_rn(pkx, xs);
            float ddy = __fsub_rn(pky, ys);
            float nrm = __fadd_rn(__fsqrt_rn(__fadd_rn(__fmul_rn(ddx, ddx),
                                                       __fmul_rn(ddy, ddy))), 1e-9f);
            float dvx = __fdiv_rn(ddx, nrm);
            float dvy = __fdiv_rn(ddy, nrm);
            float dot = __fadd_rn(__fmul_rn(pt.x, dvx), __fmul_rn(pt.y, dvy));
            if (dot > 0.9f) {
                atomicAdd(&s_z[b * HN_C + label], pt.z);
                atomicAdd(&s_n[b * HN_C + label], 1.0f);
            }
        }
    }
    __syncthreads();
    for (int i = threadIdx.x; i < HN_BC; i += 256) {
        if (s_n[i] != 0.0f) {
            atomicAdd(&g_zsum[i], s_z[i]);
            atomicAdd(&g_ninl[i], s_n[i]);
        }
    }

    // ---- last-block finalize ----
    __threadfence();
    __syncthreads();
    if (threadIdx.x == 0)
        s_last = (atomicAdd(&g_ticket, 1u) == (unsigned)(gridDim.x - 1));
    __syncthreads();
    if (!s_last) return;

    int i = threadIdx.x;
    if (i < HN_BC) {
        int b = i / HN_C;
        int c = i % HN_C;

        float cnt   = (float)(*(volatile unsigned int*)&g_counts[i]);
        float vmask = (cnt >= 500.0f && c > 0) ? 1.0f : 0.0f;

        unsigned long long key = *(volatile unsigned long long*)&g_vkey[i];
        int pk = (c == 0) ? 0 : (int)(~(unsigned)key);
        float pkx  = (float)(pk % HN_W);
        float pky  = (float)(pk / HN_W);
        float vmax = (float)(unsigned)(key >> 32);

        float zs = *(volatile float*)&g_zsum[i];
        float ni = *(volatile float*)&g_ninl[i];
        float depth  = zs / fmaxf(ni, 1.0f);
        float z_safe = (fabsf(depth) > 0.001f) ? depth : 1.0f;

        float fx = meta[b * 48 + 0];
        float fy = meta[b * 48 + 4];
        float e0 = extents[c * 3 + 0], e1 = extents[c * 3 + 1], e2 = extents[c * 3 + 2];
        float diam = sqrtf(e0 * e0 + e1 * e1 + e2 * e2);
        float half_w = 0.5f * diam * fx / z_safe;
        float half_h = 0.5f * diam * fy / z_safe;

        float* o = out + (size_t)i * 14;
        o[0] = (float)b * vmask;
        o[1] = (float)c * vmask;
        o[2] = (pkx - half_w) * vmask;
        o[3] = (pky - half_h) * vmask;
        o[4] = (pkx + half_w) * vmask;
        o[5] = (pky + half_h) * vmask;
        o[6] = vmax * vmask;
        o[7] = vmask;          // quat = (1,0,0,0) * vmask
        o[8] = 0.0f;
        o[9] = 0.0f;
        o[10] = 0.0f;
        const float* K = meta + b * 48 + 9;   // Kinv row-major 3x3
        #pragma unroll
        for (int j = 0; j < 3; j++) {
            float ray = K[j * 3 + 0] * pkx + K[j * 3 + 1] * pky + K[j * 3 + 2];
            o[11 + j] = depth * ray * vmask;
        }

        // reset accumulators for the next graph replay
        g_vkey[i]   = 0ull;
        g_zsum[i]   = 0.0f;
        g_ninl[i]   = 0.0f;
        g_counts[i] = 0u;
    }
    if (threadIdx.x == 0) g_ticket = 0u;
}

// ---------------------------------------------------------------------------
extern "C" void kernel_launch(void* const* d_in, const int* in_sizes, int n_in,
                              void* d_out, int out_size) {
    const int*   label   = (const int*)d_in[0];
    const float* vp      = (const float*)d_in[1];
    const float* extents = (const float*)d_in[2];
    // d_in[3] = poses (unused by reference)
    const float* meta    = (const float*)d_in[4];
    float* out = (float*)d_out;

    // K1: vote (one warp per point) + fused label histogram
    {
        int blocks = (HN_B * HN_P * 32 + 255) / 256;    // 3840 >= HN_HISTBLK
        hn_vote_kernel<<<blocks, 256>>>(label, vp);
    }
    // K2: argmax per voted plane + write-behind clear
    {
        dim3 grid(HN_AM_BPP, HN_NVPL);
        hn_argmax_kernel<<<grid, 256>>>();
    }
    // K3: inlier accumulation + last-block finalize
    hn_inlier_kernel<<<HN_INLBLK, 256>>>(extents, meta, out);
}

// round 6
// speedup vs baseline: 2.5446x; 1.2003x over previous
#include <cuda_runtime.h>

#define HN_B      2
#define HN_H      480
#define HN_W      640
#define HN_C      22
#define HN_HW     (HN_H * HN_W)          // 307200
#define HN_SKIP   20
#define HN_P      (HN_HW / HN_SKIP)      // 15360
#define HN_NSTEPS 200
#define HN_BC     (HN_B * HN_C)          // 44

#define HN_PLANEW  (HN_HW / 4)           // 76800 u32 words (4 px each, u8 bins)
#define HN_PLANE4  (HN_HW / 16)          // 19200 uint4 per plane
#define HN_AM_PT   5                     // uint4 per thread (argmax)
#define HN_AM_TILE (256 * HN_AM_PT)      // 1280 uint4 per block
#define HN_AM_BPP  (HN_PLANE4 / HN_AM_TILE) // 15 blocks per plane
#define HN_NVPL    42                    // voted planes (skip c==0)
#define HN_HISTBLK 600                   // vote-kernel blocks that also do the histogram
#define HN_INLBLK  ((HN_B * HN_P + 255) / 256)  // 120

// Scratch (device globals; zero-initialized at module load; every kernel_launch
// restores them to zero, so graph replays are deterministic)
__device__ unsigned int       g_hough[HN_B * HN_C * HN_PLANEW];  // uint8 bins, packed
__device__ float4             g_pts[HN_B * HN_P];   // dnx, dny, z, label(bits)
__device__ unsigned long long g_vkey[HN_BC];        // (vmax<<32) | ~pk
__device__ float              g_zsum[HN_BC];
__device__ float              g_ninl[HN_BC];
__device__ unsigned int       g_counts[HN_BC];
__device__ unsigned int       g_ticket;

// map voted-plane index j in [0,42) -> bc, skipping bc==0 and bc==22
__device__ __forceinline__ int hn_plane(int j) { return (j < 21) ? (j + 1) : (j + 2); }

// ---------------------------------------------------------------------------
// K1: hough voting (one warp per point) + fused full-image label histogram.
//     Rays exit the image monotonically; loop bounded by conservative exit
//     parameter, exact per-step bounds check stays authoritative.
//     Bins are packed uint8 (max per-bin count << 255, no carry possible).
// ---------------------------------------------------------------------------
__global__ void hn_vote_kernel(const int* __restrict__ label_2d,
                               const float* __restrict__ vertex_pred) {
    __shared__ unsigned int s_cnt[HN_BC];
    bool do_hist = (blockIdx.x < HN_HISTBLK);
    if (do_hist) {
        for (int i = threadIdx.x; i < HN_BC; i += 256) s_cnt[i] = 0u;
        __syncthreads();
        // 153600 int4 loads cover 614400 labels; 600 blocks x 256 threads
        int g4 = blockIdx.x * 256 + threadIdx.x;        // < 153600
        int4 l4 = reinterpret_cast<const int4*>(label_2d)[g4];
        int b = (g4 * 4) / HN_HW;                       // 4 labels share batch (HW%4==0)
        atomicAdd(&s_cnt[b * HN_C + l4.x], 1u);
        atomicAdd(&s_cnt[b * HN_C + l4.y], 1u);
        atomicAdd(&s_cnt[b * HN_C + l4.z], 1u);
        atomicAdd(&s_cnt[b * HN_C + l4.w], 1u);
    }

    // ---- voting ----
    int gwarp = (blockIdx.x * 256 + threadIdx.x) >> 5;
    int lane  = threadIdx.x & 31;
    if (gwarp < HN_B * HN_P) {
        int b = gwarp / HN_P;
        int p = gwarp % HN_P;
        int idx = p * HN_SKIP;
        float xs = (float)(idx % HN_W);
        float ys = (float)(idx / HN_W);

        int label = label_2d[b * HN_HW + idx];
        const float* vp = vertex_pred + ((size_t)(b * HN_HW + idx)) * (3 * HN_C) + label * 3;
        float dx = vp[0], dy = vp[1], z = vp[2];

        float nrm = __fadd_rn(__fsqrt_rn(__fadd_rn(__fmul_rn(dx, dx), __fmul_rn(dy, dy))), 1e-9f);
        float dnx = __fdiv_rn(dx, nrm);
        float dny = __fdiv_rn(dy, nrm);

        if (lane == 0) {
            float4 pt;
            pt.x = dnx; pt.y = dny; pt.z = z; pt.w = __int_as_float(label);
            g_pts[gwarp] = pt;
        }

        if (label > 0) {
            // conservative ray-exit bound: in-bounds after round-half-even
            // needs cx in [-0.5, 639.5), cy in [-0.5, 479.5); +-0.6 margin.
            float tx = (dnx > 0.0f) ? (639.6f - xs) / dnx
                     : (dnx < 0.0f) ? (-0.6f - xs) / dnx : 1e9f;
            float ty = (dny > 0.0f) ? (479.6f - ys) / dny
                     : (dny < 0.0f) ? (-0.6f - ys) / dny : 1e9f;
            float thi = fminf(fminf(tx, ty), 800.0f);
            int nb = (int)(thi * 0.25f) + 1;            // steps t=(i+1)*4 <= thi (+slack)
            if (nb > HN_NSTEPS) nb = HN_NSTEPS;

            unsigned int* hbase = g_hough + (size_t)(b * HN_C + label) * HN_PLANEW;
            #pragma unroll 2
            for (int i = lane; i < nb; i += 32) {
                float t  = (float)(i + 1) * 4.0f;
                float cx = __fadd_rn(xs, __fmul_rn(dnx, t));
                float cy = __fadd_rn(ys, __fmul_rn(dny, t));
                int cxi = __float2int_rn(cx);           // round-half-even == jnp.round
                int cyi = __float2int_rn(cy);
                if (cxi >= 0 && cxi < HN_W && cyi >= 0 && cyi < HN_H) {
                    // packed uint8 bins: 4 px per word
                    atomicAdd(&hbase[cyi * (HN_W / 4) + (cxi >> 2)],
                              1u << ((cxi & 3) * 8));
                }
            }
        }
    }

    if (do_hist) {
        __syncthreads();
        for (int i = threadIdx.x; i < HN_BC; i += 256)
            if (s_cnt[i]) atomicAdd(&g_counts[i], s_cnt[i]);
    }
}

// ---------------------------------------------------------------------------
// K2: argmax over the 42 voted planes + write-behind clear for next replay.
//     grid (15, 42), 256 thr, 5 uint4 loads/thread (MLP=5).
//     Pass 1: per-thread byte max via __vmaxu4 (1 op/word).
//     Pass 2: first (lowest-pixel) byte equal to the max via __vcmpeq4+ffs.
//     Block reduce on packed key (val<<32 | ~idx); atomicMax into g_vkey.
// ---------------------------------------------------------------------------
__global__ void hn_argmax_kernel() {
    int bc = hn_plane(blockIdx.y);
    uint4* h4 = reinterpret_cast<uint4*>(g_hough)
              + (size_t)bc * HN_PLANE4 + blockIdx.x * HN_AM_TILE;

    uint4 r[HN_AM_PT];
    #pragma unroll
    for (int o = 0; o < HN_AM_PT; o++)
        r[o] = h4[threadIdx.x + o * 256];               // all loads in flight

    // pass 1: per-thread max byte
    unsigned int m4 = 0u;
    #pragma unroll
    for (int o = 0; o < HN_AM_PT; o++) {
        m4 = __vmaxu4(m4, r[o].x);
        m4 = __vmaxu4(m4, r[o].y);
        m4 = __vmaxu4(m4, r[o].z);
        m4 = __vmaxu4(m4, r[o].w);
    }
    unsigned int tb = __vmaxu4(m4, m4 >> 16);
    tb = __vmaxu4(tb, tb >> 8);
    unsigned int bv = tb & 0xffu;
    unsigned int pat = bv * 0x01010101u;

    // pass 2: first pixel index (ascending) holding bv
    int bi = -1;
    #pragma unroll
    for (int o = 0; o < HN_AM_PT; o++) {
        int pb = (blockIdx.x * HN_AM_TILE + threadIdx.x + o * 256) * 16;
        unsigned int eq;
        eq = __vcmpeq4(r[o].x, pat);
        if (bi < 0 && eq) bi = pb + ((__ffs(eq) - 1) >> 3);
        eq = __vcmpeq4(r[o].y, pat);
        if (bi < 0 && eq) bi = pb + 4 + ((__ffs(eq) - 1) >> 3);
        eq = __vcmpeq4(r[o].z, pat);
        if (bi < 0 && eq) bi = pb + 8 + ((__ffs(eq) - 1) >> 3);
        eq = __vcmpeq4(r[o].w, pat);
        if (bi < 0 && eq) bi = pb + 12 + ((__ffs(eq) - 1) >> 3);
    }

    // clear tile for the next run (write-behind)
    uint4 z4 = make_uint4(0u, 0u, 0u, 0u);
    #pragma unroll
    for (int o = 0; o < HN_AM_PT; o++)
        h4[threadIdx.x + o * 256] = z4;

    unsigned long long key = ((unsigned long long)bv << 32) | (unsigned)(~bi);

    __shared__ unsigned long long sk[256];
    sk[threadIdx.x] = key;
    __syncthreads();
    #pragma unroll
    for (int s = 128; s > 0; s >>= 1) {
        if (threadIdx.x < s) {
            unsigned long long o = sk[threadIdx.x + s];
            if (o > sk[threadIdx.x]) sk[threadIdx.x] = o;
        }
        __syncthreads();
    }
    if (threadIdx.x == 0)
        atomicMax(&g_vkey[bc], sk[0]);
}

// ---------------------------------------------------------------------------
// K3: inlier accumulation + fused finalize in the last block (ticket pattern).
//     The last block also resets all small accumulators for the next replay.
// ---------------------------------------------------------------------------
__global__ void hn_inlier_kernel(const float* __restrict__ extents,
                                 const float* __restrict__ meta,
                                 float* __restrict__ out) {
    __shared__ float s_z[HN_BC];
    __shared__ float s_n[HN_BC];
    __shared__ bool  s_last;
    for (int i = threadIdx.x; i < HN_BC; i += 256) { s_z[i] = 0.0f; s_n[i] = 0.0f; }
    __syncthreads();

    int g = blockIdx.x * 256 + threadIdx.x;
    if (g < HN_B * HN_P) {
        int b = g / HN_P;
        int p = g % HN_P;
        int idx = p * HN_SKIP;
        float xs = (float)(idx % HN_W);
        float ys = (float)(idx / HN_W);

        float4 pt = g_pts[g];
        int label = __float_as_int(pt.w);
        if (label > 0) {
            int pk = (int)(~(unsigned)g_vkey[b * HN_C + label]);
            float pkx = (float)(pk % HN_W);
            float pky = (float)(pk / HN_W);
            float ddx = __fsub_rn(pkx, xs);
            float ddy = __fsub_rn(pky, ys);
            float nrm = __fadd_rn(__fsqrt_rn(__fadd_rn(__fmul_rn(ddx, ddx),
                                                       __fmul_rn(ddy, ddy))), 1e-9f);
            float dvx = __fdiv_rn(ddx, nrm);
            float dvy = __fdiv_rn(ddy, nrm);
            float dot = __fadd_rn(__fmul_rn(pt.x, dvx), __fmul_rn(pt.y, dvy));
            if (dot > 0.9f) {
                atomicAdd(&s_z[b * HN_C + label], pt.z);
                atomicAdd(&s_n[b * HN_C + label], 1.0f);
            }
        }
    }
    __syncthreads();
    for (int i = threadIdx.x; i < HN_BC; i += 256) {
        if (s_n[i] != 0.0f) {
            atomicAdd(&g_zsum[i], s_z[i]);
            atomicAdd(&g_ninl[i], s_n[i]);
        }
    }

    // ---- last-block finalize ----
    __threadfence();
    __syncthreads();
    if (threadIdx.x == 0)
        s_last = (atomicAdd(&g_ticket, 1u) == (unsigned)(gridDim.x - 1));
    __syncthreads();
    if (!s_last) return;

    int i = threadIdx.x;
    if (i < HN_BC) {
        int b = i / HN_C;
        int c = i % HN_C;

        float cnt   = (float)(*(volatile unsigned int*)&g_counts[i]);
        float vmask = (cnt >= 500.0f && c > 0) ? 1.0f : 0.0f;

        unsigned long long key = *(volatile unsigned long long*)&g_vkey[i];
        int pk = (c == 0) ? 0 : (int)(~(unsigned)key);
        float pkx  = (float)(pk % HN_W);
        float pky  = (float)(pk / HN_W);
        float vmax = (float)(unsigned)(key >> 32);

        float zs = *(volatile float*)&g_zsum[i];
        float ni = *(volatile float*)&g_ninl[i];
        float depth  = zs / fmaxf(ni, 1.0f);
        float z_safe = (fabsf(depth) > 0.001f) ? depth : 1.0f;

        float fx = meta[b * 48 + 0];
        float fy = meta[b * 48 + 4];
        float e0 = extents[c * 3 + 0], e1 = extents[c * 3 + 1], e2 = extents[c * 3 + 2];
        float diam = sqrtf(e0 * e0 + e1 * e1 + e2 * e2);
        float half_w = 0.5f * diam * fx / z_safe;
        float half_h = 0.5f * diam * fy / z_safe;

        float* o = out + (size_t)i * 14;
        o[0] = (float)b * vmask;
        o[1] = (float)c * vmask;
        o[2] = (pkx - half_w) * vmask;
        o[3] = (pky - half_h) * vmask;
        o[4] = (pkx + half_w) * vmask;
        o[5] = (pky + half_h) * vmask;
        o[6] = vmax * vmask;
        o[7] = vmask;          // quat = (1,0,0,0) * vmask
        o[8] = 0.0f;
        o[9] = 0.0f;
        o[10] = 0.0f;
        const float* K = meta + b * 48 + 9;   // Kinv row-major 3x3
        #pragma unroll
        for (int j = 0; j < 3; j++) {
            float ray = K[j * 3 + 0] * pkx + K[j * 3 + 1] * pky + K[j * 3 + 2];
            o[11 + j] = depth * ray * vmask;
        }

        // reset accumulators for the next graph replay
        g_vkey[i]   = 0ull;
        g_zsum[i]   = 0.0f;
        g_ninl[i]   = 0.0f;
        g_counts[i] = 0u;
    }
    if (threadIdx.x == 0) g_ticket = 0u;
}

// ---------------------------------------------------------------------------
extern "C" void kernel_launch(void* const* d_in, const int* in_sizes, int n_in,
                              void* d_out, int out_size) {
    const int*   label   = (const int*)d_in[0];
    const float* vp      = (const float*)d_in[1];
    const float* extents = (const float*)d_in[2];
    // d_in[3] = poses (unused by reference)
    const float* meta    = (const float*)d_in[4];
    float* out = (float*)d_out;

    // K1: vote (one warp per point) + fused label histogram
    {
        int blocks = (HN_B * HN_P * 32 + 255) / 256;    // 3840 >= HN_HISTBLK
        hn_vote_kernel<<<blocks, 256>>>(label, vp);
    }
    // K2: argmax per voted plane + write-behind clear
    {
        dim3 grid(HN_AM_BPP, HN_NVPL);
        hn_argmax_kernel<<<grid, 256>>>();
    }
    // K3: inlier accumulation + last-block finalize
    hn_inlier_kernel<<<HN_INLBLK, 256>>>(extents, meta, out);
}